// round 15
// baseline (speedup 1.0000x reference)
#include <cuda_runtime.h>
#include <cuda_fp16.h>
#include <math.h>
#include <float.h>
#include <stdint.h>
#include <limits.h>

// Problem constants
#define NROWS 32768
#define KC    8192
#define DIM   512

#define DECAYF 0.99f
#define OMDF   0.01f
#define EPSF   1e-5f

#define NCAND 48              // 16 owner threads x top-3 per row
#define RERANK_THRESH 10.0f   // int8 distance err sigma ~1.2 -> 8.6 sigma gate
#define QSCALE 16.0f          // acc = 256*(x.e)_q ; s*128 = en*128 - acc

// ============================================================
// scratch (device globals)
// ============================================================
__device__ float g_enorm2[KC];
__device__ int   g_enorm2i[KC];       // round(128 * ||e||^2)
__device__ unsigned int g_cand[NROWS * NCAND];
__device__ float g_counts[KC];
__device__ float g_dw[KC * DIM];
__device__ float g_cs_pre[KC];
__device__ float g_loss_sum;
__device__ float g_n_sum;
__device__ float g_plogp_sum;

// int8 operands, row-major [rows][512]
__device__ int8_t g_xs8[NROWS * DIM];
__device__ int8_t g_es8[KC * DIM];

// ---- output layout (O_EMB/O_W only 8-byte aligned -> float2 there) ----
#define O_Q    0
#define O_LOSS (NROWS * DIM)
#define O_PERP (O_LOSS + 1)
#define O_EMB  (O_PERP + 1)
#define O_CS   (O_EMB + KC * DIM)
#define O_W    (O_CS + KC)

// ============================================================
// PTX helpers (baseline compute_100 = sm_80+/sm_90+ features only)
// ============================================================
__device__ __forceinline__ uint32_t smem_u32(const void* p) {
    uint32_t a;
    asm("{ .reg .u64 t; cvta.to.shared.u64 t, %1; cvt.u32.u64 %0, t; }" : "=r"(a) : "l"(p));
    return a;
}
__device__ __forceinline__ void cp16(uint32_t dst, const void* src) {
    asm volatile("cp.async.cg.shared.global [%0], [%1], 16;" :: "r"(dst), "l"(src) : "memory");
}
__device__ __forceinline__ void cp_commit() { asm volatile("cp.async.commit_group;" ::: "memory"); }
__device__ __forceinline__ void cp_wait0()  { asm volatile("cp.async.wait_group 0;" ::: "memory"); }

__device__ __forceinline__ void ldsm4(uint32_t* r, uint32_t addr) {
    asm volatile("ldmatrix.sync.aligned.m8n8.x4.shared.b16 {%0,%1,%2,%3}, [%4];"
        : "=r"(r[0]), "=r"(r[1]), "=r"(r[2]), "=r"(r[3]) : "r"(addr));
}
__device__ __forceinline__ void imma16832(int* c, const uint32_t* a, const uint32_t* b) {
    asm volatile(
        "mma.sync.aligned.m16n8k32.row.col.s32.s8.s8.s32 "
        "{%0,%1,%2,%3}, {%4,%5,%6,%7}, {%8,%9}, {%0,%1,%2,%3};"
        : "+r"(c[0]), "+r"(c[1]), "+r"(c[2]), "+r"(c[3])
        : "r"(a[0]), "r"(a[1]), "r"(a[2]), "r"(a[3]), "r"(b[0]), "r"(b[1]));
}

// ============================================================
// K0: fused prep — int8 convert, zero accumulators, E norms
// ============================================================
__device__ __forceinline__ uint32_t quant4(float4 v) {
    int q0 = max(-127, min(127, __float2int_rn(v.x * QSCALE)));
    int q1 = max(-127, min(127, __float2int_rn(v.y * QSCALE)));
    int q2 = max(-127, min(127, __float2int_rn(v.z * QSCALE)));
    int q3 = max(-127, min(127, __float2int_rn(v.w * QSCALE)));
    return (uint32_t)(q0 & 0xff) | ((uint32_t)(q1 & 0xff) << 8)
         | ((uint32_t)(q2 & 0xff) << 16) | ((uint32_t)(q3 & 0xff) << 24);
}

__global__ __launch_bounds__(256) void k_prep(const float* __restrict__ X,
                                              const float* __restrict__ E) {
    const int gid = blockIdx.x * blockDim.x + threadIdx.x;
    const int stride = gridDim.x * blockDim.x;
    const int n4x = NROWS * DIM / 4;
    const int n4e = KC * DIM / 4;
    for (int g = gid; g < n4x; g += stride)
        ((uint32_t*)g_xs8)[g] = quant4(*(const float4*)(X + (size_t)g * 4));
    for (int g = gid; g < n4e; g += stride)
        ((uint32_t*)g_es8)[g] = quant4(*(const float4*)(E + (size_t)g * 4));
    for (int i = gid; i < KC * DIM / 4; i += stride)
        *(float4*)(g_dw + (size_t)i * 4) = make_float4(0.f, 0.f, 0.f, 0.f);
    if (gid < KC) g_counts[gid] = 0.0f;
    if (gid == 0) { g_loss_sum = 0.0f; g_n_sum = 0.0f; g_plogp_sum = 0.0f; }

    // E row norms: one warp per code row
    const int lane = threadIdx.x & 31;
    const int warp = gid >> 5;
    const int nwarps = stride >> 5;
    for (int k = warp; k < KC; k += nwarps) {
        const float* row = E + (size_t)k * DIM;
        float s = 0.0f;
        #pragma unroll
        for (int d = lane * 4; d < DIM; d += 128) {
            float4 v = *(const float4*)(row + d);
            s = fmaf(v.x, v.x, s); s = fmaf(v.y, v.y, s);
            s = fmaf(v.z, v.z, s); s = fmaf(v.w, v.w, s);
        }
        #pragma unroll
        for (int o = 16; o; o >>= 1) s += __shfl_xor_sync(0xffffffffu, s, o);
        if (lane == 0) {
            g_enorm2[k] = s;
            g_enorm2i[k] = __float2int_rn(s * 128.0f);
        }
    }
}

// ============================================================
// K3: int8 IMMA GEMM, 512-thread CTA, 256 rows resident.
// 16 warps as 4 (64-row) x 4 (32-col); warp tile 64x32.
// Top-3 per (thread, 8 rowslots): v1/v2/v3/i1/i2 in registers,
// i3 in a smem plane (written only on rare 3rd-place entries).
// smem: A 135168 + B 2x10240 + i3 16384 = 172032. 1 CTA/SM, grid 128.
// ============================================================
#define A_STRIDE 528
#define A_BYTES  (256 * A_STRIDE)          // 135168
#define SM_B     A_BYTES
#define TILE_BB  10240                     // 128 * 80
#define SM_I3    (SM_B + 2 * TILE_BB)      // 155648
#define SMEM_MMA (SM_I3 + 8 * 512 * 4)     // 172032

__global__ __launch_bounds__(512, 1) void k_argmin_mma() {
    extern __shared__ char smem[];
    const uint32_t sb = smem_u32(smem);
    const int tid = threadIdx.x;
    const int lane = tid & 31;
    const int wid = tid >> 5;
    const int wr = wid >> 2;            // 0..3 : 64-row band
    const int wc = wid & 3;             // 0..3 : 32-col band
    const int mt = blockIdx.x;

    // ---- stage A resident: 256 rows x 512B = 8192 x 16B segs ----
    {
        const int8_t* Ab = g_xs8 + (size_t)mt * 256 * DIM;
        #pragma unroll
        for (int i = 0; i < 16; ++i) {
            int seg = tid + i * 512;
            int r = seg >> 5, cs = seg & 31;
            cp16(sb + r * A_STRIDE + cs * 16, Ab + (size_t)r * DIM + cs * 16);
        }
        cp_commit();
    }

    const uint32_t offA = sb + (uint32_t)((wr * 64 + (lane & 15)) * A_STRIDE
                                          + (lane >> 4) * 16);
    const uint32_t offB = sb + (uint32_t)(SM_B + (wc * 32 + (lane & 7) + ((lane >> 4) & 1) * 8) * 80
                                          + ((lane >> 3) & 1) * 16);

    uint32_t* i3p = (uint32_t*)(smem + SM_I3);   // [slot][tid]

    // top-3 state: values + top-2 indices in registers, i3 in smem
    int v1[8], v2[8], v3[8];
    uint32_t i12[8];
    #pragma unroll
    for (int s = 0; s < 8; ++s) { v1[s] = INT_MAX; v2[s] = INT_MAX; v3[s] = INT_MAX; i12[s] = 0; }

    // stage B chunk 0 of tile 0 (512 segs, 1 per thread)
    {
        const int r = tid >> 2, cs = tid & 3;
        cp16(sb + SM_B + r * 80 + cs * 16, g_es8 + (size_t)r * DIM + cs * 16);
        cp_commit();
    }

    #pragma unroll 1
    for (int t = 0; t < KC / 128; ++t) {
        const int8_t* Bb = g_es8 + (size_t)t * 128 * DIM;
        int acc[4][4][4];
        #pragma unroll
        for (int m = 0; m < 4; ++m)
            #pragma unroll
            for (int n = 0; n < 4; ++n)
                #pragma unroll
                for (int r = 0; r < 4; ++r) acc[m][n][r] = 0;

        #pragma unroll 1
        for (int c = 0; c < 8; ++c) {
            cp_wait0();
            __syncthreads();
            if (c + 1 < 8 || t + 1 < KC / 128) {
                const int8_t* Bn = (c + 1 < 8) ? Bb : (g_es8 + (size_t)(t + 1) * 128 * DIM);
                const int cn = (c + 1) & 7;
                const uint32_t bdst = sb + SM_B + ((c + 1) & 1) * TILE_BB;
                const int r = tid >> 2, cs = tid & 3;
                cp16(bdst + r * 80 + cs * 16, Bn + (size_t)r * DIM + cn * 64 + cs * 16);
                cp_commit();
            }
            const uint32_t bbuf = (uint32_t)((c & 1) * TILE_BB);
            const uint32_t abase = offA + c * 64;
            #pragma unroll
            for (int ks = 0; ks < 2; ++ks) {
                uint32_t aF[4][4], bF[2][4];
                #pragma unroll
                for (int m = 0; m < 4; ++m)
                    ldsm4(aF[m], abase + m * (16 * A_STRIDE) + ks * 32);
                #pragma unroll
                for (int p = 0; p < 2; ++p)
                    ldsm4(bF[p], offB + bbuf + p * (16 * 80) + ks * 32);
                #pragma unroll
                for (int m = 0; m < 4; ++m)
                    #pragma unroll
                    for (int n = 0; n < 4; ++n)
                        imma16832(acc[m][n], aF[m], &bF[n >> 1][(n & 1) * 2]);
            }
        }

        // integer-domain top-3 fold (common path: single register compare)
        #pragma unroll
        for (int m = 0; m < 4; ++m)
            #pragma unroll
            for (int h = 0; h < 2; ++h) {
                const int slot = m * 2 + h;
                int a1 = v1[slot], a2 = v2[slot], a3 = v3[slot];
                uint32_t p = i12[slot];
                int j1 = p >> 16, j2 = p & 0xffff;
                #pragma unroll
                for (int n = 0; n < 4; ++n) {
                    const int colb = t * 128 + wc * 32 + n * 8 + 2 * (lane & 3);
                    #pragma unroll
                    for (int q = 0; q < 2; ++q) {
                        const int col = colb + q;
                        const int s = __ldg(&g_enorm2i[col]) - acc[m][n][h * 2 + q];
                        if (s < a3) {
                            if (s < a1) {
                                i3p[slot * 512 + tid] = (uint32_t)j2;
                                a3 = a2; a2 = a1; j2 = j1; a1 = s; j1 = col;
                            } else if (s < a2) {
                                i3p[slot * 512 + tid] = (uint32_t)j2;
                                a3 = a2; a2 = s; j2 = col;
                            } else {
                                i3p[slot * 512 + tid] = (uint32_t)col;
                                a3 = s;
                            }
                        }
                    }
                }
                v1[slot] = a1; v2[slot] = a2; v3[slot] = a3;
                i12[slot] = (uint32_t)(j1 << 16) | (uint32_t)j2;
            }
    }

    // dump candidates: key = (f16(s_i/128) << 16) | col ; [row][48]
    __syncthreads();
    uint32_t* keys = (uint32_t*)smem;            // reuse A region: 256*48*4 = 48KB
    #pragma unroll
    for (int m = 0; m < 4; ++m)
        #pragma unroll
        for (int h = 0; h < 2; ++h) {
            const int slot = m * 2 + h;
            float f1 = (float)v1[slot] * 0.0078125f;
            float f2 = (float)v2[slot] * 0.0078125f;
            float f3 = (float)v3[slot] * 0.0078125f;
            uint32_t p = i12[slot];
            uint32_t j3 = i3p[slot * 512 + tid];
            int row = wr * 64 + m * 16 + h * 8 + (lane >> 2);
            int ent = (wc * 4 + (lane & 3)) * 3;
            keys[row * 48 + ent + 0] =
                ((uint32_t)__half_as_ushort(__float2half_rn(f1)) << 16) | (p >> 16);
            keys[row * 48 + ent + 1] =
                ((uint32_t)__half_as_ushort(__float2half_rn(f2)) << 16) | (p & 0xffff);
            keys[row * 48 + ent + 2] =
                ((uint32_t)__half_as_ushort(__float2half_rn(f3)) << 16) | (j3 & 0xffff);
        }
    __syncthreads();
    #pragma unroll
    for (int j = 0; j < 24; ++j) {
        int lin = tid + j * 512;                 // 0..12287
        g_cand[(size_t)mt * (256 * NCAND) + lin] = keys[lin];
    }
}

// ============================================================
// K3b: barrier-free warp-per-row rerank + gather (48 candidates).
// ============================================================
__global__ __launch_bounds__(256) void k_rerank(const float* __restrict__ X,
                                                const float* __restrict__ E,
                                                float* __restrict__ out) {
    __shared__ float lsum[8];
    const int tid = threadIdx.x;
    const int lane = tid & 31;
    const int wrp = tid >> 5;
    const int row = blockIdx.x * 8 + wrp;

    unsigned int key1 = g_cand[(size_t)row * NCAND + lane];
    unsigned int key2 = (lane < NCAND - 32) ? g_cand[(size_t)row * NCAND + 32 + lane]
                                            : 0xFFFFFFFFu;
    const unsigned int mkey = min(__reduce_min_sync(0xffffffffu, key1),
                                  __reduce_min_sync(0xffffffffu, key2));
    const float thresh = __half2float(__ushort_as_half((unsigned short)(mkey >> 16)))
                         + RERANK_THRESH;

    float4 x[4];
    #pragma unroll
    for (int j = 0; j < 4; ++j)
        x[j] = *(const float4*)(X + (size_t)row * DIM + j * 128 + lane * 4);

    float bests = FLT_MAX;
    int   bestc = 0x7fffffff;
    #pragma unroll 1
    for (int c = 0; c < NCAND; ++c) {
        const unsigned int kc = (c < 32) ? __shfl_sync(0xffffffffu, key1, c)
                                         : __shfl_sync(0xffffffffu, key2, c - 32);
        const float v = __half2float(__ushort_as_half((unsigned short)(kc >> 16)));
        if (v <= thresh) {
            const int col = (int)(kc & 0xffffu);
            const float* er = E + (size_t)col * DIM;
            float dot = 0.0f;
            #pragma unroll
            for (int j = 0; j < 4; ++j) {
                float4 e = *(const float4*)(er + j * 128 + lane * 4);
                dot = fmaf(x[j].x, e.x, dot); dot = fmaf(x[j].y, e.y, dot);
                dot = fmaf(x[j].z, e.z, dot); dot = fmaf(x[j].w, e.w, dot);
            }
            #pragma unroll
            for (int o = 16; o; o >>= 1) dot += __shfl_xor_sync(0xffffffffu, dot, o);
            const float s = fmaf(-2.0f, dot, __ldg(&g_enorm2[col]));
            if (s < bests || (s == bests && col < bestc)) { bests = s; bestc = col; }
        }
    }

    const float* er = E + (size_t)bestc * DIM;
    float* dwr = g_dw + (size_t)bestc * DIM;
    float ls = 0.0f;
    #pragma unroll
    for (int j = 0; j < 4; ++j) {
        const int d = j * 128 + lane * 4;
        float4 q = *(const float4*)(er + d);
        *(float4*)(out + O_Q + (size_t)row * DIM + d) = q;
        atomicAdd((float4*)(dwr + d), x[j]);
        float dx = q.x - x[j].x, dy = q.y - x[j].y;
        float dz = q.z - x[j].z, dw = q.w - x[j].w;
        ls += dx * dx + dy * dy + dz * dz + dw * dw;
    }
    #pragma unroll
    for (int o = 16; o; o >>= 1) ls += __shfl_xor_sync(0xffffffffu, ls, o);
    if (lane == 0) {
        lsum[wrp] = ls;
        atomicAdd(&g_counts[bestc], 1.0f);
    }
    __syncthreads();
    if (tid == 0) {
        float s = 0.0f;
        #pragma unroll
        for (int w = 0; w < 8; ++w) s += lsum[w];
        atomicAdd(&g_loss_sum, s);
    }
}

// ============================================================
// K5a: EMA cluster-size pre + global sums
// ============================================================
__global__ __launch_bounds__(256) void k_stats1(const float* __restrict__ cs_in) {
    __shared__ float sn[8], sp[8];
    int k = blockIdx.x * 256 + threadIdx.x;
    float cnt = g_counts[k];
    float pre = fmaf(cs_in[k], DECAYF, OMDF * cnt);
    g_cs_pre[k] = pre;
    float p = cnt * (1.0f / (float)NROWS);
    float pl = p * logf(p + 1e-10f);
    float ns = pre, ps = pl;
    #pragma unroll
    for (int o = 16; o; o >>= 1) {
        ns += __shfl_xor_sync(0xffffffffu, ns, o);
        ps += __shfl_xor_sync(0xffffffffu, ps, o);
    }
    int lane = threadIdx.x & 31, warp = threadIdx.x >> 5;
    if (lane == 0) { sn[warp] = ns; sp[warp] = ps; }
    __syncthreads();
    if (threadIdx.x == 0) {
        float a = 0.0f, b = 0.0f;
        #pragma unroll
        for (int w = 0; w < 8; ++w) { a += sn[w]; b += sp[w]; }
        atomicAdd(&g_n_sum, a);
        atomicAdd(&g_plogp_sum, b);
    }
}

// ============================================================
// K6: finalize: new_cs, loss, perplexity, new_w, new_embedding
// ============================================================
__global__ __launch_bounds__(256) void k_final(const float* __restrict__ ema_w,
                                               float* __restrict__ out) {
    const float n = g_n_sum;
    const float inv_den = 1.0f / (n + (float)KC * EPSF);
    if (blockIdx.x == 0 && threadIdx.x == 0) {
        out[O_LOSS] = 0.25f * (g_loss_sum / (float)(NROWS * DIM));
        out[O_PERP] = expf(-g_plogp_sum);
    }
    int i = blockIdx.x * blockDim.x + threadIdx.x;
    int total = KC * DIM / 4;
    int stride = gridDim.x * blockDim.x;
    for (; i < total; i += stride) {
        int e = i * 4;
        int k = e >> 9;
        float ncs = (g_cs_pre[k] + EPSF) * inv_den * n;
        if ((e & (DIM - 1)) == 0) out[O_CS + k] = ncs;
        float4 w  = *(const float4*)(ema_w + e);
        float4 dv = *(const float4*)(g_dw + e);
        float4 nw;
        nw.x = fmaf(w.x, DECAYF, OMDF * dv.x);
        nw.y = fmaf(w.y, DECAYF, OMDF * dv.y);
        nw.z = fmaf(w.z, DECAYF, OMDF * dv.z);
        nw.w = fmaf(w.w, DECAYF, OMDF * dv.w);
        *(float2*)(out + O_W + e)     = make_float2(nw.x, nw.y);
        *(float2*)(out + O_W + e + 2) = make_float2(nw.z, nw.w);
        float inv = 1.0f / ncs;
        *(float2*)(out + O_EMB + e)     = make_float2(nw.x * inv, nw.y * inv);
        *(float2*)(out + O_EMB + e + 2) = make_float2(nw.z * inv, nw.w * inv);
    }
}

// ============================================================
extern "C" void kernel_launch(void* const* d_in, const int* in_sizes, int n_in,
                              void* d_out, int out_size) {
    const float* X     = (const float*)d_in[0];
    const float* E     = (const float*)d_in[1];
    const float* cs    = (const float*)d_in[2];
    const float* ema_w = (const float*)d_in[3];
    float* out = (float*)d_out;

    cudaFuncSetAttribute(k_argmin_mma, cudaFuncAttributeMaxDynamicSharedMemorySize, SMEM_MMA);

    k_prep  <<<4096, 256>>>(X, E);
    k_argmin_mma<<<NROWS / 256, 512, SMEM_MMA>>>();
    k_rerank<<<NROWS / 8, 256>>>(X, E, out);
    k_stats1<<<KC / 256, 256>>>(cs);
    k_final <<<2048, 256>>>(ema_w, out);
}

// round 16
// speedup vs baseline: 1.2101x; 1.2101x over previous
#include <cuda_runtime.h>
#include <cuda_fp16.h>
#include <math.h>
#include <float.h>
#include <stdint.h>
#include <limits.h>

// Problem constants
#define NROWS 32768
#define KC    8192
#define DIM   512

#define DECAYF 0.99f
#define OMDF   0.01f
#define EPSF   1e-5f

#define NCAND 24              // 8 owner threads x top-3 per row
#define RERANK_THRESH 10.0f   // int8 distance err sigma ~1.2 -> 8.6 sigma gate
#define QSCALE 16.0f          // acc = 256*(x.e)_q ; s*128 = en*128 - acc

// ============================================================
// scratch (device globals)
// ============================================================
__device__ float g_enorm2[KC];
__device__ int   g_enorm2i[KC];       // round(128 * ||e||^2)
__device__ unsigned int g_cand[NROWS * NCAND];
__device__ float g_counts[KC];
__device__ float g_dw[KC * DIM];
__device__ float g_cs_pre[KC];
__device__ float g_loss_sum;
__device__ float g_n_sum;
__device__ float g_plogp_sum;

// int8 operands, row-major [rows][512]
__device__ int8_t g_xs8[NROWS * DIM];
__device__ int8_t g_es8[KC * DIM];

// ---- output layout (O_EMB/O_W only 8-byte aligned -> float2 there) ----
#define O_Q    0
#define O_LOSS (NROWS * DIM)
#define O_PERP (O_LOSS + 1)
#define O_EMB  (O_PERP + 1)
#define O_CS   (O_EMB + KC * DIM)
#define O_W    (O_CS + KC)

// ============================================================
// PTX helpers (baseline compute_100 = sm_80+/sm_90+ features only)
// ============================================================
__device__ __forceinline__ uint32_t smem_u32(const void* p) {
    uint32_t a;
    asm("{ .reg .u64 t; cvta.to.shared.u64 t, %1; cvt.u32.u64 %0, t; }" : "=r"(a) : "l"(p));
    return a;
}
__device__ __forceinline__ void cp16(uint32_t dst, const void* src) {
    asm volatile("cp.async.cg.shared.global [%0], [%1], 16;" :: "r"(dst), "l"(src) : "memory");
}
__device__ __forceinline__ void cp_commit() { asm volatile("cp.async.commit_group;" ::: "memory"); }
__device__ __forceinline__ void cp_wait0()  { asm volatile("cp.async.wait_group 0;" ::: "memory"); }

__device__ __forceinline__ void ldsm4(uint32_t* r, uint32_t addr) {
    asm volatile("ldmatrix.sync.aligned.m8n8.x4.shared.b16 {%0,%1,%2,%3}, [%4];"
        : "=r"(r[0]), "=r"(r[1]), "=r"(r[2]), "=r"(r[3]) : "r"(addr));
}
__device__ __forceinline__ void imma16832(int* c, const uint32_t* a, const uint32_t* b) {
    asm volatile(
        "mma.sync.aligned.m16n8k32.row.col.s32.s8.s8.s32 "
        "{%0,%1,%2,%3}, {%4,%5,%6,%7}, {%8,%9}, {%0,%1,%2,%3};"
        : "+r"(c[0]), "+r"(c[1]), "+r"(c[2]), "+r"(c[3])
        : "r"(a[0]), "r"(a[1]), "r"(a[2]), "r"(a[3]), "r"(b[0]), "r"(b[1]));
}

// ============================================================
// K0: fused prep — int8 convert, zero accumulators, E norms
// ============================================================
__device__ __forceinline__ uint32_t quant4(float4 v) {
    int q0 = max(-127, min(127, __float2int_rn(v.x * QSCALE)));
    int q1 = max(-127, min(127, __float2int_rn(v.y * QSCALE)));
    int q2 = max(-127, min(127, __float2int_rn(v.z * QSCALE)));
    int q3 = max(-127, min(127, __float2int_rn(v.w * QSCALE)));
    return (uint32_t)(q0 & 0xff) | ((uint32_t)(q1 & 0xff) << 8)
         | ((uint32_t)(q2 & 0xff) << 16) | ((uint32_t)(q3 & 0xff) << 24);
}

__global__ __launch_bounds__(256) void k_prep(const float* __restrict__ X,
                                              const float* __restrict__ E) {
    const int gid = blockIdx.x * blockDim.x + threadIdx.x;
    const int stride = gridDim.x * blockDim.x;
    const int n4x = NROWS * DIM / 4;
    const int n4e = KC * DIM / 4;
    for (int g = gid; g < n4x; g += stride)
        ((uint32_t*)g_xs8)[g] = quant4(*(const float4*)(X + (size_t)g * 4));
    for (int g = gid; g < n4e; g += stride)
        ((uint32_t*)g_es8)[g] = quant4(*(const float4*)(E + (size_t)g * 4));
    for (int i = gid; i < KC * DIM / 4; i += stride)
        *(float4*)(g_dw + (size_t)i * 4) = make_float4(0.f, 0.f, 0.f, 0.f);
    if (gid < KC) g_counts[gid] = 0.0f;
    if (gid == 0) { g_loss_sum = 0.0f; g_n_sum = 0.0f; g_plogp_sum = 0.0f; }

    // E row norms: one warp per code row
    const int lane = threadIdx.x & 31;
    const int warp = gid >> 5;
    const int nwarps = stride >> 5;
    for (int k = warp; k < KC; k += nwarps) {
        const float* row = E + (size_t)k * DIM;
        float s = 0.0f;
        #pragma unroll
        for (int d = lane * 4; d < DIM; d += 128) {
            float4 v = *(const float4*)(row + d);
            s = fmaf(v.x, v.x, s); s = fmaf(v.y, v.y, s);
            s = fmaf(v.z, v.z, s); s = fmaf(v.w, v.w, s);
        }
        #pragma unroll
        for (int o = 16; o; o >>= 1) s += __shfl_xor_sync(0xffffffffu, s, o);
        if (lane == 0) {
            g_enorm2[k] = s;
            g_enorm2i[k] = __float2int_rn(s * 128.0f);
        }
    }
}

// ============================================================
// K3: int8 IMMA GEMM (verified R12 config), A resident 128 rows,
// 256 threads, 2 CTAs/SM, warp tile 32x64, smem top-3 planes.
// R16 delta: enorm2i hoisted to 16 registers per tile (was 64 ldg).
// ============================================================
#define SM_A     0
#define A_STRIDE 528
#define A_BYTES  (128 * A_STRIDE)          // 67584
#define SM_B     A_BYTES
#define TILE_BB  10240                     // 128 * 80
#define TOPV     (SM_B + 2 * TILE_BB)      // int planes [3][4][256] = 12 KB
#define TOPI12   (TOPV + 12288)
#define TOPI3    (TOPI12 + 4096)
#define SMEM_MMA (TOPI3 + 4096)            // 108544

__global__ __launch_bounds__(256, 2) void k_argmin_mma() {
    extern __shared__ char smem[];
    const uint32_t sb = smem_u32(smem);
    const int tid = threadIdx.x;
    const int lane = tid & 31;
    const int wid = tid >> 5;
    const int wr = wid >> 1;            // 0..3 : 32-row band
    const int wc = wid & 1;             // 0..1 : 64-col band
    const int mt = blockIdx.x;

    // ---- stage A resident ----
    {
        const int8_t* Ab = g_xs8 + (size_t)mt * 128 * DIM;
        #pragma unroll
        for (int i = 0; i < 16; ++i) {
            int seg = tid + i * 256;
            int r = seg >> 5, cs = seg & 31;
            cp16(sb + SM_A + r * A_STRIDE + cs * 16, Ab + (size_t)r * DIM + cs * 16);
        }
        cp_commit();
    }

    const uint32_t offA = sb + (uint32_t)(SM_A + (wr * 32 + (lane & 15)) * A_STRIDE
                                          + (lane >> 4) * 16);
    const uint32_t offB = sb + (uint32_t)(SM_B + (wc * 64 + (lane & 7) + ((lane >> 4) & 1) * 8) * 80
                                          + ((lane >> 3) & 1) * 16);

    int* vp = (int*)(smem + TOPV);
    uint32_t* ip12 = (uint32_t*)(smem + TOPI12);
    uint32_t* ip3  = (uint32_t*)(smem + TOPI3);
    #pragma unroll
    for (int j = 0; j < 3; ++j)
        #pragma unroll
        for (int s = 0; s < 4; ++s) vp[(j * 4 + s) * 256 + tid] = INT_MAX;
    #pragma unroll
    for (int s = 0; s < 4; ++s) { ip12[s * 256 + tid] = 0; ip3[s * 256 + tid] = 0; }

    // stage B chunk 0 of tile 0
    {
        const int8_t* Bb = g_es8;
        #pragma unroll
        for (int i = 0; i < 2; ++i) {
            int seg = tid + i * 256;
            int r = seg >> 2, cs = seg & 3;
            cp16(sb + SM_B + r * 80 + cs * 16, Bb + (size_t)r * DIM + cs * 16);
        }
        cp_commit();
    }

    #pragma unroll 1
    for (int t = 0; t < KC / 128; ++t) {
        const int8_t* Bb = g_es8 + (size_t)t * 128 * DIM;
        int acc[2][8][4];
        #pragma unroll
        for (int m = 0; m < 2; ++m)
            #pragma unroll
            for (int n = 0; n < 8; ++n)
                #pragma unroll
                for (int r = 0; r < 4; ++r) acc[m][n][r] = 0;

        #pragma unroll 1
        for (int c = 0; c < 8; ++c) {
            cp_wait0();
            __syncthreads();
            if (c + 1 < 8 || t + 1 < KC / 128) {
                const int8_t* Bn = (c + 1 < 8) ? Bb : (g_es8 + (size_t)(t + 1) * 128 * DIM);
                const int cn = (c + 1) & 7;
                const uint32_t bdst = sb + SM_B + ((c + 1) & 1) * TILE_BB;
                #pragma unroll
                for (int i = 0; i < 2; ++i) {
                    int seg = tid + i * 256;
                    int r = seg >> 2, cs = seg & 3;
                    cp16(bdst + r * 80 + cs * 16, Bn + (size_t)r * DIM + cn * 64 + cs * 16);
                }
                cp_commit();
            }
            const uint32_t bbuf = (uint32_t)((c & 1) * TILE_BB);
            const uint32_t abase = offA + c * 64;
            #pragma unroll
            for (int ks = 0; ks < 2; ++ks) {
                uint32_t aF[2][4], bF[4][4];
                #pragma unroll
                for (int m = 0; m < 2; ++m)
                    ldsm4(aF[m], abase + m * (16 * A_STRIDE) + ks * 32);
                #pragma unroll
                for (int p = 0; p < 4; ++p)
                    ldsm4(bF[p], offB + bbuf + p * (16 * 80) + ks * 32);
                #pragma unroll
                for (int m = 0; m < 2; ++m)
                    #pragma unroll
                    for (int p = 0; p < 4; ++p) {
                        imma16832(acc[m][p * 2],     aF[m], &bF[p][0]);
                        imma16832(acc[m][p * 2 + 1], aF[m], &bF[p][2]);
                    }
            }
        }

        // hoisted: 16 distinct enorm2i values per tile (shared by all 4 slots)
        int en[16];
        #pragma unroll
        for (int f = 0; f < 8; ++f) {
            const int colb = t * 128 + wc * 64 + (f >> 1) * 16 + (f & 1) * 8 + 2 * (lane & 3);
            en[f * 2]     = __ldg(&g_enorm2i[colb]);
            en[f * 2 + 1] = __ldg(&g_enorm2i[colb + 1]);
        }

        // integer-domain fold: s_i = en - acc ; rare-entry top-3 chain
        #pragma unroll
        for (int m = 0; m < 2; ++m)
            #pragma unroll
            for (int h = 0; h < 2; ++h) {
                const int slot = m * 2 + h;
                int v1 = vp[(0 * 4 + slot) * 256 + tid];
                int v2 = vp[(1 * 4 + slot) * 256 + tid];
                int v3 = vp[(2 * 4 + slot) * 256 + tid];
                uint32_t p12 = ip12[slot * 256 + tid];
                uint32_t p3  = ip3[slot * 256 + tid];
                int i1 = p12 >> 16, i2 = p12 & 0xffff, i3 = (int)p3;
                #pragma unroll
                for (int f = 0; f < 8; ++f) {
                    const int colb = t * 128 + wc * 64 + (f >> 1) * 16 + (f & 1) * 8
                                     + 2 * (lane & 3);
                    #pragma unroll
                    for (int q = 0; q < 2; ++q) {
                        const int col = colb + q;
                        const int s = en[f * 2 + q] - acc[m][f][h * 2 + q];
                        if (s < v3) {
                            if (s < v1)      { v3 = v2; i3 = i2; v2 = v1; i2 = i1; v1 = s; i1 = col; }
                            else if (s < v2) { v3 = v2; i3 = i2; v2 = s; i2 = col; }
                            else             { v3 = s; i3 = col; }
                        }
                    }
                }
                vp[(0 * 4 + slot) * 256 + tid] = v1;
                vp[(1 * 4 + slot) * 256 + tid] = v2;
                vp[(2 * 4 + slot) * 256 + tid] = v3;
                ip12[slot * 256 + tid] = (uint32_t)(i1 << 16) | (uint32_t)i2;
                ip3[slot * 256 + tid]  = (uint32_t)i3;
            }
    }

    // dump candidates: key = (f16(s_i/128) << 16) | col ; [row][24]
    __syncthreads();
    uint32_t* keys = (uint32_t*)smem;            // reuse A region, 12 KB
    #pragma unroll
    for (int m = 0; m < 2; ++m)
        #pragma unroll
        for (int h = 0; h < 2; ++h) {
            const int slot = m * 2 + h;
            float v1 = (float)vp[(0 * 4 + slot) * 256 + tid] * 0.0078125f;
            float v2 = (float)vp[(1 * 4 + slot) * 256 + tid] * 0.0078125f;
            float v3 = (float)vp[(2 * 4 + slot) * 256 + tid] * 0.0078125f;
            uint32_t p12 = ip12[slot * 256 + tid];
            uint32_t p3  = ip3[slot * 256 + tid];
            int row = wr * 32 + m * 16 + h * 8 + (lane >> 2);
            int ent = (wc * 4 + (lane & 3)) * 3;
            keys[row * 24 + ent + 0] =
                ((uint32_t)__half_as_ushort(__float2half_rn(v1)) << 16) | (p12 >> 16);
            keys[row * 24 + ent + 1] =
                ((uint32_t)__half_as_ushort(__float2half_rn(v2)) << 16) | (p12 & 0xffff);
            keys[row * 24 + ent + 2] =
                ((uint32_t)__half_as_ushort(__float2half_rn(v3)) << 16) | (p3 & 0xffff);
        }
    __syncthreads();
    #pragma unroll
    for (int j = 0; j < 12; ++j) {
        int lin = tid + j * 256;                 // 0..3071
        g_cand[(size_t)mt * (128 * NCAND) + lin] = keys[lin];
    }
}

// ============================================================
// K3b: barrier-free warp-per-row rerank + gather (24 candidates).
// ============================================================
__global__ __launch_bounds__(256) void k_rerank(const float* __restrict__ X,
                                                const float* __restrict__ E,
                                                float* __restrict__ out) {
    __shared__ float lsum[8];
    const int tid = threadIdx.x;
    const int lane = tid & 31;
    const int wrp = tid >> 5;
    const int row = blockIdx.x * 8 + wrp;

    unsigned int key = (lane < NCAND) ? g_cand[(size_t)row * NCAND + lane] : 0xFFFFFFFFu;
    const unsigned int mkey = __reduce_min_sync(0xffffffffu, key);
    const float thresh = __half2float(__ushort_as_half((unsigned short)(mkey >> 16)))
                         + RERANK_THRESH;

    float4 x[4];
    #pragma unroll
    for (int j = 0; j < 4; ++j)
        x[j] = *(const float4*)(X + (size_t)row * DIM + j * 128 + lane * 4);

    float bests = FLT_MAX;
    int   bestc = 0x7fffffff;
    #pragma unroll 1
    for (int c = 0; c < NCAND; ++c) {
        const unsigned int kc = __shfl_sync(0xffffffffu, key, c);
        const float v = __half2float(__ushort_as_half((unsigned short)(kc >> 16)));
        if (v <= thresh) {
            const int col = (int)(kc & 0xffffu);
            const float* er = E + (size_t)col * DIM;
            float dot = 0.0f;
            #pragma unroll
            for (int j = 0; j < 4; ++j) {
                float4 e = *(const float4*)(er + j * 128 + lane * 4);
                dot = fmaf(x[j].x, e.x, dot); dot = fmaf(x[j].y, e.y, dot);
                dot = fmaf(x[j].z, e.z, dot); dot = fmaf(x[j].w, e.w, dot);
            }
            #pragma unroll
            for (int o = 16; o; o >>= 1) dot += __shfl_xor_sync(0xffffffffu, dot, o);
            const float s = fmaf(-2.0f, dot, __ldg(&g_enorm2[col]));
            if (s < bests || (s == bests && col < bestc)) { bests = s; bestc = col; }
        }
    }

    const float* er = E + (size_t)bestc * DIM;
    float* dwr = g_dw + (size_t)bestc * DIM;
    float ls = 0.0f;
    #pragma unroll
    for (int j = 0; j < 4; ++j) {
        const int d = j * 128 + lane * 4;
        float4 q = *(const float4*)(er + d);
        *(float4*)(out + O_Q + (size_t)row * DIM + d) = q;
        atomicAdd((float4*)(dwr + d), x[j]);
        float dx = q.x - x[j].x, dy = q.y - x[j].y;
        float dz = q.z - x[j].z, dw = q.w - x[j].w;
        ls += dx * dx + dy * dy + dz * dz + dw * dw;
    }
    #pragma unroll
    for (int o = 16; o; o >>= 1) ls += __shfl_xor_sync(0xffffffffu, ls, o);
    if (lane == 0) {
        lsum[wrp] = ls;
        atomicAdd(&g_counts[bestc], 1.0f);
    }
    __syncthreads();
    if (tid == 0) {
        float s = 0.0f;
        #pragma unroll
        for (int w = 0; w < 8; ++w) s += lsum[w];
        atomicAdd(&g_loss_sum, s);
    }
}

// ============================================================
// K5a: EMA cluster-size pre + global sums
// ============================================================
__global__ __launch_bounds__(256) void k_stats1(const float* __restrict__ cs_in) {
    __shared__ float sn[8], sp[8];
    int k = blockIdx.x * 256 + threadIdx.x;
    float cnt = g_counts[k];
    float pre = fmaf(cs_in[k], DECAYF, OMDF * cnt);
    g_cs_pre[k] = pre;
    float p = cnt * (1.0f / (float)NROWS);
    float pl = p * logf(p + 1e-10f);
    float ns = pre, ps = pl;
    #pragma unroll
    for (int o = 16; o; o >>= 1) {
        ns += __shfl_xor_sync(0xffffffffu, ns, o);
        ps += __shfl_xor_sync(0xffffffffu, ps, o);
    }
    int lane = threadIdx.x & 31, warp = threadIdx.x >> 5;
    if (lane == 0) { sn[warp] = ns; sp[warp] = ps; }
    __syncthreads();
    if (threadIdx.x == 0) {
        float a = 0.0f, b = 0.0f;
        #pragma unroll
        for (int w = 0; w < 8; ++w) { a += sn[w]; b += sp[w]; }
        atomicAdd(&g_n_sum, a);
        atomicAdd(&g_plogp_sum, b);
    }
}

// ============================================================
// K6: finalize: new_cs, loss, perplexity, new_w, new_embedding
// ============================================================
__global__ __launch_bounds__(256) void k_final(const float* __restrict__ ema_w,
                                               float* __restrict__ out) {
    const float n = g_n_sum;
    const float inv_den = 1.0f / (n + (float)KC * EPSF);
    if (blockIdx.x == 0 && threadIdx.x == 0) {
        out[O_LOSS] = 0.25f * (g_loss_sum / (float)(NROWS * DIM));
        out[O_PERP] = expf(-g_plogp_sum);
    }
    int i = blockIdx.x * blockDim.x + threadIdx.x;
    int total = KC * DIM / 4;
    int stride = gridDim.x * blockDim.x;
    for (; i < total; i += stride) {
        int e = i * 4;
        int k = e >> 9;
        float ncs = (g_cs_pre[k] + EPSF) * inv_den * n;
        if ((e & (DIM - 1)) == 0) out[O_CS + k] = ncs;
        float4 w  = *(const float4*)(ema_w + e);
        float4 dv = *(const float4*)(g_dw + e);
        float4 nw;
        nw.x = fmaf(w.x, DECAYF, OMDF * dv.x);
        nw.y = fmaf(w.y, DECAYF, OMDF * dv.y);
        nw.z = fmaf(w.z, DECAYF, OMDF * dv.z);
        nw.w = fmaf(w.w, DECAYF, OMDF * dv.w);
        *(float2*)(out + O_W + e)     = make_float2(nw.x, nw.y);
        *(float2*)(out + O_W + e + 2) = make_float2(nw.z, nw.w);
        float inv = 1.0f / ncs;
        *(float2*)(out + O_EMB + e)     = make_float2(nw.x * inv, nw.y * inv);
        *(float2*)(out + O_EMB + e + 2) = make_float2(nw.z * inv, nw.w * inv);
    }
}

// ============================================================
extern "C" void kernel_launch(void* const* d_in, const int* in_sizes, int n_in,
                              void* d_out, int out_size) {
    const float* X     = (const float*)d_in[0];
    const float* E     = (const float*)d_in[1];
    const float* cs    = (const float*)d_in[2];
    const float* ema_w = (const float*)d_in[3];
    float* out = (float*)d_out;

    cudaFuncSetAttribute(k_argmin_mma, cudaFuncAttributeMaxDynamicSharedMemorySize, SMEM_MMA);

    k_prep  <<<4096, 256>>>(X, E);
    k_argmin_mma<<<NROWS / 128, 256, SMEM_MMA>>>();
    k_rerank<<<NROWS / 8, 256>>>(X, E, out);
    k_stats1<<<KC / 256, 256>>>(cs);
    k_final <<<2048, 256>>>(ema_w, out);
}

// round 17
// speedup vs baseline: 1.2489x; 1.0321x over previous
#include <cuda_runtime.h>
#include <cuda_fp16.h>
#include <math.h>
#include <float.h>
#include <stdint.h>
#include <limits.h>

// Problem constants
#define NROWS 32768
#define KC    8192
#define DIM   512

#define DECAYF 0.99f
#define OMDF   0.01f
#define EPSF   1e-5f

#define NCAND 24              // 8 owner threads x top-3 per row
#define RERANK_THRESH 10.0f   // int8 distance err sigma ~1.2 -> 8.6 sigma gate
#define QSCALE 16.0f          // acc = 256*(x.e)_q ; s*128 = en*128 - acc

// ============================================================
// scratch (device globals)
// ============================================================
__device__ float g_enorm2[KC];
__device__ int   g_enorm2i[KC];       // round(128 * ||e||^2)
__device__ unsigned int g_cand[NROWS * NCAND];
__device__ float g_counts[KC];
__device__ float g_dw[KC * DIM];
__device__ float g_cs_pre[KC];
__device__ float g_loss_sum;
__device__ float g_n_sum;
__device__ float g_plogp_sum;

// int8 operands, row-major [rows][512]
__device__ int8_t g_xs8[NROWS * DIM];
__device__ int8_t g_es8[KC * DIM];

// ---- output layout (O_EMB/O_W only 8-byte aligned -> float2 there) ----
#define O_Q    0
#define O_LOSS (NROWS * DIM)
#define O_PERP (O_LOSS + 1)
#define O_EMB  (O_PERP + 1)
#define O_CS   (O_EMB + KC * DIM)
#define O_W    (O_CS + KC)

// ============================================================
// PTX helpers (baseline compute_100 = sm_80+/sm_90+ features only)
// ============================================================
__device__ __forceinline__ uint32_t smem_u32(const void* p) {
    uint32_t a;
    asm("{ .reg .u64 t; cvta.to.shared.u64 t, %1; cvt.u32.u64 %0, t; }" : "=r"(a) : "l"(p));
    return a;
}
__device__ __forceinline__ void cp16(uint32_t dst, const void* src) {
    asm volatile("cp.async.cg.shared.global [%0], [%1], 16;" :: "r"(dst), "l"(src) : "memory");
}
__device__ __forceinline__ void cp_commit() { asm volatile("cp.async.commit_group;" ::: "memory"); }
__device__ __forceinline__ void cp_wait0()  { asm volatile("cp.async.wait_group 0;" ::: "memory"); }
__device__ __forceinline__ void cp_wait1()  { asm volatile("cp.async.wait_group 1;" ::: "memory"); }

__device__ __forceinline__ void ldsm4(uint32_t* r, uint32_t addr) {
    asm volatile("ldmatrix.sync.aligned.m8n8.x4.shared.b16 {%0,%1,%2,%3}, [%4];"
        : "=r"(r[0]), "=r"(r[1]), "=r"(r[2]), "=r"(r[3]) : "r"(addr));
}
__device__ __forceinline__ void imma16832(int* c, const uint32_t* a, const uint32_t* b) {
    asm volatile(
        "mma.sync.aligned.m16n8k32.row.col.s32.s8.s8.s32 "
        "{%0,%1,%2,%3}, {%4,%5,%6,%7}, {%8,%9}, {%0,%1,%2,%3};"
        : "+r"(c[0]), "+r"(c[1]), "+r"(c[2]), "+r"(c[3])
        : "r"(a[0]), "r"(a[1]), "r"(a[2]), "r"(a[3]), "r"(b[0]), "r"(b[1]));
}

// ============================================================
// K0: fused prep — int8 convert, zero accumulators, E norms
// ============================================================
__device__ __forceinline__ uint32_t quant4(float4 v) {
    int q0 = max(-127, min(127, __float2int_rn(v.x * QSCALE)));
    int q1 = max(-127, min(127, __float2int_rn(v.y * QSCALE)));
    int q2 = max(-127, min(127, __float2int_rn(v.z * QSCALE)));
    int q3 = max(-127, min(127, __float2int_rn(v.w * QSCALE)));
    return (uint32_t)(q0 & 0xff) | ((uint32_t)(q1 & 0xff) << 8)
         | ((uint32_t)(q2 & 0xff) << 16) | ((uint32_t)(q3 & 0xff) << 24);
}

__global__ __launch_bounds__(256) void k_prep(const float* __restrict__ X,
                                              const float* __restrict__ E) {
    const int gid = blockIdx.x * blockDim.x + threadIdx.x;
    const int stride = gridDim.x * blockDim.x;
    const int n4x = NROWS * DIM / 4;
    const int n4e = KC * DIM / 4;
    for (int g = gid; g < n4x; g += stride)
        ((uint32_t*)g_xs8)[g] = quant4(*(const float4*)(X + (size_t)g * 4));
    for (int g = gid; g < n4e; g += stride)
        ((uint32_t*)g_es8)[g] = quant4(*(const float4*)(E + (size_t)g * 4));
    for (int i = gid; i < KC * DIM / 4; i += stride)
        *(float4*)(g_dw + (size_t)i * 4) = make_float4(0.f, 0.f, 0.f, 0.f);
    if (gid < KC) g_counts[gid] = 0.0f;
    if (gid == 0) { g_loss_sum = 0.0f; g_n_sum = 0.0f; g_plogp_sum = 0.0f; }

    // E row norms: one warp per code row
    const int lane = threadIdx.x & 31;
    const int warp = gid >> 5;
    const int nwarps = stride >> 5;
    for (int k = warp; k < KC; k += nwarps) {
        const float* row = E + (size_t)k * DIM;
        float s = 0.0f;
        #pragma unroll
        for (int d = lane * 4; d < DIM; d += 128) {
            float4 v = *(const float4*)(row + d);
            s = fmaf(v.x, v.x, s); s = fmaf(v.y, v.y, s);
            s = fmaf(v.z, v.z, s); s = fmaf(v.w, v.w, s);
        }
        #pragma unroll
        for (int o = 16; o; o >>= 1) s += __shfl_xor_sync(0xffffffffu, s, o);
        if (lane == 0) {
            g_enorm2[k] = s;
            g_enorm2i[k] = __float2int_rn(s * 128.0f);
        }
    }
}

// ============================================================
// K3: int8 IMMA GEMM. R17 deltas vs R16:
//  - B TRIPLE-buffered + cp.async.wait_group 1 (2 chunks in flight)
//  - top-3 fold fully register-resident (only 4 row slots)
// smem: A 67584 + B 3x10240 = 98304 -> still 2 CTAs/SM.
// ============================================================
#define SM_A     0
#define A_STRIDE 528
#define A_BYTES  (128 * A_STRIDE)          // 67584
#define SM_B     A_BYTES
#define TILE_BB  10240                     // 128 * 80
#define SMEM_MMA (SM_B + 3 * TILE_BB)      // 98304
#define NCHUNK   (KC / 128 * 8)            // 512 global chunks

__device__ __forceinline__ void stage_b(uint32_t sb, int g, int tid) {
    const int8_t* Bn = g_es8 + (size_t)(g >> 3) * 128 * DIM;
    const int cn = g & 7;
    const uint32_t bdst = sb + SM_B + (uint32_t)((g % 3) * TILE_BB);
    #pragma unroll
    for (int i = 0; i < 2; ++i) {
        int seg = tid + i * 256;
        int r = seg >> 2, cs = seg & 3;
        cp16(bdst + r * 80 + cs * 16, Bn + (size_t)r * DIM + cn * 64 + cs * 16);
    }
    cp_commit();
}

__global__ __launch_bounds__(256, 2) void k_argmin_mma() {
    extern __shared__ char smem[];
    const uint32_t sb = smem_u32(smem);
    const int tid = threadIdx.x;
    const int lane = tid & 31;
    const int wid = tid >> 5;
    const int wr = wid >> 1;            // 0..3 : 32-row band
    const int wc = wid & 1;             // 0..1 : 64-col band
    const int mt = blockIdx.x;

    // ---- stage A resident ----
    {
        const int8_t* Ab = g_xs8 + (size_t)mt * 128 * DIM;
        #pragma unroll
        for (int i = 0; i < 16; ++i) {
            int seg = tid + i * 256;
            int r = seg >> 5, cs = seg & 31;
            cp16(sb + SM_A + r * A_STRIDE + cs * 16, Ab + (size_t)r * DIM + cs * 16);
        }
        cp_commit();
    }

    const uint32_t offA = sb + (uint32_t)(SM_A + (wr * 32 + (lane & 15)) * A_STRIDE
                                          + (lane >> 4) * 16);
    const uint32_t offB = sb + (uint32_t)(SM_B + (wc * 64 + (lane & 7) + ((lane >> 4) & 1) * 8) * 80
                                          + ((lane >> 3) & 1) * 16);

    // register-resident top-3 state, 4 row slots
    int v1[4], v2[4], v3[4];
    uint32_t i12[4], i3r[4];
    #pragma unroll
    for (int s = 0; s < 4; ++s) {
        v1[s] = INT_MAX; v2[s] = INT_MAX; v3[s] = INT_MAX; i12[s] = 0; i3r[s] = 0;
    }

    // prologue: two B chunks in flight
    stage_b(sb, 0, tid);
    stage_b(sb, 1, tid);

    #pragma unroll 1
    for (int t = 0; t < KC / 128; ++t) {
        int acc[2][8][4];
        #pragma unroll
        for (int m = 0; m < 2; ++m)
            #pragma unroll
            for (int n = 0; n < 8; ++n)
                #pragma unroll
                for (int r = 0; r < 4; ++r) acc[m][n][r] = 0;

        #pragma unroll 1
        for (int c = 0; c < 8; ++c) {
            const int g = t * 8 + c;
            cp_wait1();                     // chunk g resident; g+1 may be in flight
            __syncthreads();
            if (g + 2 < NCHUNK) stage_b(sb, g + 2, tid);
            const uint32_t bbuf = (uint32_t)((g % 3) * TILE_BB);
            const uint32_t abase = offA + c * 64;
            #pragma unroll
            for (int ks = 0; ks < 2; ++ks) {
                uint32_t aF[2][4], bF[4][4];
                #pragma unroll
                for (int m = 0; m < 2; ++m)
                    ldsm4(aF[m], abase + m * (16 * A_STRIDE) + ks * 32);
                #pragma unroll
                for (int p = 0; p < 4; ++p)
                    ldsm4(bF[p], offB + bbuf + p * (16 * 80) + ks * 32);
                #pragma unroll
                for (int m = 0; m < 2; ++m)
                    #pragma unroll
                    for (int p = 0; p < 4; ++p) {
                        imma16832(acc[m][p * 2],     aF[m], &bF[p][0]);
                        imma16832(acc[m][p * 2 + 1], aF[m], &bF[p][2]);
                    }
            }
        }

        // hoisted: 16 distinct enorm2i values per tile
        int en[16];
        #pragma unroll
        for (int f = 0; f < 8; ++f) {
            const int colb = t * 128 + wc * 64 + (f >> 1) * 16 + (f & 1) * 8 + 2 * (lane & 3);
            en[f * 2]     = __ldg(&g_enorm2i[colb]);
            en[f * 2 + 1] = __ldg(&g_enorm2i[colb + 1]);
        }

        // register top-3 fold
        #pragma unroll
        for (int m = 0; m < 2; ++m)
            #pragma unroll
            for (int h = 0; h < 2; ++h) {
                const int slot = m * 2 + h;
                int a1 = v1[slot], a2 = v2[slot], a3 = v3[slot];
                uint32_t p = i12[slot];
                int j1 = p >> 16, j2 = p & 0xffff, j3 = (int)i3r[slot];
                #pragma unroll
                for (int f = 0; f < 8; ++f) {
                    const int colb = t * 128 + wc * 64 + (f >> 1) * 16 + (f & 1) * 8
                                     + 2 * (lane & 3);
                    #pragma unroll
                    for (int q = 0; q < 2; ++q) {
                        const int col = colb + q;
                        const int s = en[f * 2 + q] - acc[m][f][h * 2 + q];
                        if (s < a3) {
                            if (s < a1)      { a3 = a2; j3 = j2; a2 = a1; j2 = j1; a1 = s; j1 = col; }
                            else if (s < a2) { a3 = a2; j3 = j2; a2 = s; j2 = col; }
                            else             { a3 = s; j3 = col; }
                        }
                    }
                }
                v1[slot] = a1; v2[slot] = a2; v3[slot] = a3;
                i12[slot] = (uint32_t)(j1 << 16) | (uint32_t)j2;
                i3r[slot] = (uint32_t)j3;
            }
    }

    // dump candidates: key = (f16(s_i/128) << 16) | col ; [row][24]
    __syncthreads();
    uint32_t* keys = (uint32_t*)smem;            // reuse A region, 12 KB
    #pragma unroll
    for (int m = 0; m < 2; ++m)
        #pragma unroll
        for (int h = 0; h < 2; ++h) {
            const int slot = m * 2 + h;
            float f1 = (float)v1[slot] * 0.0078125f;
            float f2 = (float)v2[slot] * 0.0078125f;
            float f3 = (float)v3[slot] * 0.0078125f;
            uint32_t p = i12[slot];
            int row = wr * 32 + m * 16 + h * 8 + (lane >> 2);
            int ent = (wc * 4 + (lane & 3)) * 3;
            keys[row * 24 + ent + 0] =
                ((uint32_t)__half_as_ushort(__float2half_rn(f1)) << 16) | (p >> 16);
            keys[row * 24 + ent + 1] =
                ((uint32_t)__half_as_ushort(__float2half_rn(f2)) << 16) | (p & 0xffff);
            keys[row * 24 + ent + 2] =
                ((uint32_t)__half_as_ushort(__float2half_rn(f3)) << 16) | (i3r[slot] & 0xffff);
        }
    __syncthreads();
    #pragma unroll
    for (int j = 0; j < 12; ++j) {
        int lin = tid + j * 256;                 // 0..3071
        g_cand[(size_t)mt * (128 * NCAND) + lin] = keys[lin];
    }
}

// ============================================================
// K3b: barrier-free warp-per-row rerank + gather (24 candidates).
// ============================================================
__global__ __launch_bounds__(256) void k_rerank(const float* __restrict__ X,
                                                const float* __restrict__ E,
                                                float* __restrict__ out) {
    __shared__ float lsum[8];
    const int tid = threadIdx.x;
    const int lane = tid & 31;
    const int wrp = tid >> 5;
    const int row = blockIdx.x * 8 + wrp;

    unsigned int key = (lane < NCAND) ? g_cand[(size_t)row * NCAND + lane] : 0xFFFFFFFFu;
    const unsigned int mkey = __reduce_min_sync(0xffffffffu, key);
    const float thresh = __half2float(__ushort_as_half((unsigned short)(mkey >> 16)))
                         + RERANK_THRESH;

    float4 x[4];
    #pragma unroll
    for (int j = 0; j < 4; ++j)
        x[j] = *(const float4*)(X + (size_t)row * DIM + j * 128 + lane * 4);

    float bests = FLT_MAX;
    int   bestc = 0x7fffffff;
    #pragma unroll 1
    for (int c = 0; c < NCAND; ++c) {
        const unsigned int kc = __shfl_sync(0xffffffffu, key, c);
        const float v = __half2float(__ushort_as_half((unsigned short)(kc >> 16)));
        if (v <= thresh) {
            const int col = (int)(kc & 0xffffu);
            const float* er = E + (size_t)col * DIM;
            float dot = 0.0f;
            #pragma unroll
            for (int j = 0; j < 4; ++j) {
                float4 e = *(const float4*)(er + j * 128 + lane * 4);
                dot = fmaf(x[j].x, e.x, dot); dot = fmaf(x[j].y, e.y, dot);
                dot = fmaf(x[j].z, e.z, dot); dot = fmaf(x[j].w, e.w, dot);
            }
            #pragma unroll
            for (int o = 16; o; o >>= 1) dot += __shfl_xor_sync(0xffffffffu, dot, o);
            const float s = fmaf(-2.0f, dot, __ldg(&g_enorm2[col]));
            if (s < bests || (s == bests && col < bestc)) { bests = s; bestc = col; }
        }
    }

    const float* er = E + (size_t)bestc * DIM;
    float* dwr = g_dw + (size_t)bestc * DIM;
    float ls = 0.0f;
    #pragma unroll
    for (int j = 0; j < 4; ++j) {
        const int d = j * 128 + lane * 4;
        float4 q = *(const float4*)(er + d);
        *(float4*)(out + O_Q + (size_t)row * DIM + d) = q;
        atomicAdd((float4*)(dwr + d), x[j]);
        float dx = q.x - x[j].x, dy = q.y - x[j].y;
        float dz = q.z - x[j].z, dw = q.w - x[j].w;
        ls += dx * dx + dy * dy + dz * dz + dw * dw;
    }
    #pragma unroll
    for (int o = 16; o; o >>= 1) ls += __shfl_xor_sync(0xffffffffu, ls, o);
    if (lane == 0) {
        lsum[wrp] = ls;
        atomicAdd(&g_counts[bestc], 1.0f);
    }
    __syncthreads();
    if (tid == 0) {
        float s = 0.0f;
        #pragma unroll
        for (int w = 0; w < 8; ++w) s += lsum[w];
        atomicAdd(&g_loss_sum, s);
    }
}

// ============================================================
// K5a: EMA cluster-size pre + global sums
// ============================================================
__global__ __launch_bounds__(256) void k_stats1(const float* __restrict__ cs_in) {
    __shared__ float sn[8], sp[8];
    int k = blockIdx.x * 256 + threadIdx.x;
    float cnt = g_counts[k];
    float pre = fmaf(cs_in[k], DECAYF, OMDF * cnt);
    g_cs_pre[k] = pre;
    float p = cnt * (1.0f / (float)NROWS);
    float pl = p * logf(p + 1e-10f);
    float ns = pre, ps = pl;
    #pragma unroll
    for (int o = 16; o; o >>= 1) {
        ns += __shfl_xor_sync(0xffffffffu, ns, o);
        ps += __shfl_xor_sync(0xffffffffu, ps, o);
    }
    int lane = threadIdx.x & 31, warp = threadIdx.x >> 5;
    if (lane == 0) { sn[warp] = ns; sp[warp] = ps; }
    __syncthreads();
    if (threadIdx.x == 0) {
        float a = 0.0f, b = 0.0f;
        #pragma unroll
        for (int w = 0; w < 8; ++w) { a += sn[w]; b += sp[w]; }
        atomicAdd(&g_n_sum, a);
        atomicAdd(&g_plogp_sum, b);
    }
}

// ============================================================
// K6: finalize: new_cs, loss, perplexity, new_w, new_embedding
// ============================================================
__global__ __launch_bounds__(256) void k_final(const float* __restrict__ ema_w,
                                               float* __restrict__ out) {
    const float n = g_n_sum;
    const float inv_den = 1.0f / (n + (float)KC * EPSF);
    if (blockIdx.x == 0 && threadIdx.x == 0) {
        out[O_LOSS] = 0.25f * (g_loss_sum / (float)(NROWS * DIM));
        out[O_PERP] = expf(-g_plogp_sum);
    }
    int i = blockIdx.x * blockDim.x + threadIdx.x;
    int total = KC * DIM / 4;
    int stride = gridDim.x * blockDim.x;
    for (; i < total; i += stride) {
        int e = i * 4;
        int k = e >> 9;
        float ncs = (g_cs_pre[k] + EPSF) * inv_den * n;
        if ((e & (DIM - 1)) == 0) out[O_CS + k] = ncs;
        float4 w  = *(const float4*)(ema_w + e);
        float4 dv = *(const float4*)(g_dw + e);
        float4 nw;
        nw.x = fmaf(w.x, DECAYF, OMDF * dv.x);
        nw.y = fmaf(w.y, DECAYF, OMDF * dv.y);
        nw.z = fmaf(w.z, DECAYF, OMDF * dv.z);
        nw.w = fmaf(w.w, DECAYF, OMDF * dv.w);
        *(float2*)(out + O_W + e)     = make_float2(nw.x, nw.y);
        *(float2*)(out + O_W + e + 2) = make_float2(nw.z, nw.w);
        float inv = 1.0f / ncs;
        *(float2*)(out + O_EMB + e)     = make_float2(nw.x * inv, nw.y * inv);
        *(float2*)(out + O_EMB + e + 2) = make_float2(nw.z * inv, nw.w * inv);
    }
}

// ============================================================
extern "C" void kernel_launch(void* const* d_in, const int* in_sizes, int n_in,
                              void* d_out, int out_size) {
    const float* X     = (const float*)d_in[0];
    const float* E     = (const float*)d_in[1];
    const float* cs    = (const float*)d_in[2];
    const float* ema_w = (const float*)d_in[3];
    float* out = (float*)d_out;

    cudaFuncSetAttribute(k_argmin_mma, cudaFuncAttributeMaxDynamicSharedMemorySize, SMEM_MMA);

    k_prep  <<<4096, 256>>>(X, E);
    k_argmin_mma<<<NROWS / 128, 256, SMEM_MMA>>>();
    k_rerank<<<NROWS / 8, 256>>>(X, E, out);
    k_stats1<<<KC / 256, 256>>>(cs);
    k_final <<<2048, 256>>>(ema_w, out);
}